// round 1
// baseline (speedup 1.0000x reference)
#include <cuda_runtime.h>
#include <cstdint>

#define NTOK 2048
#define HD   768
#define ID   1536
#define N1   3072
#define NE   16
#define TK   4
#define NPAIR (NTOK*TK)

// ---------------- scratch (static, no allocs) ----------------
__device__ __align__(16) float g_t[(size_t)NTOK*HD];      // rmsnorm'd tokens (tf32-rounded)
__device__ __align__(16) float g_act[(size_t)NPAIR*ID];   // swiglu activations per pair
__device__ __align__(16) float g_y[(size_t)NPAIR*HD];     // weighted expert outputs per pair
__device__ int   g_top_idx[NTOK*TK];
__device__ float g_top_w[NTOK*TK];
__device__ int   g_cnt[NE];
__device__ int   g_off[NE+1];
__device__ int   g_cur[NE];
__device__ int   g_pair_tok[NPAIR];
__device__ float g_pair_w[NPAIR];
__device__ int   g_pos[NPAIR];

__device__ __forceinline__ unsigned f2tf(float x){
    unsigned u; asm("cvt.rna.tf32.f32 %0, %1;" : "=r"(u) : "f"(x)); return u;
}

__device__ __forceinline__ void mma8(float c[4], const unsigned a[4], const unsigned b[2]){
    asm volatile(
        "mma.sync.aligned.m16n8k8.row.col.f32.tf32.tf32.f32 "
        "{%0,%1,%2,%3},{%4,%5,%6,%7},{%8,%9},{%0,%1,%2,%3};\n"
        : "+f"(c[0]), "+f"(c[1]), "+f"(c[2]), "+f"(c[3])
        : "r"(a[0]), "r"(a[1]), "r"(a[2]), "r"(a[3]), "r"(b[0]), "r"(b[1]));
}

// ---------------- kernel 0: reset counters ----------------
__global__ void k_reset(){
    int i = threadIdx.x;
    if (i < NE){ g_cnt[i] = 0; g_cur[i] = 0; }
}

// ---------------- kernel 1: rmsnorm + gate + top4 ----------------
__global__ void __launch_bounds__(256) k_norm_gate(
    const float* __restrict__ x, const float* __restrict__ nsc,
    const float* __restrict__ gw, const float* __restrict__ gb)
{
    __shared__ float sh_t[HD];
    __shared__ float red[8];
    __shared__ float sh_g[NE];
    const int tok = blockIdx.x, tid = threadIdx.x;
    const int lane = tid & 31, wid = tid >> 5;
    const float* xr = x + (size_t)tok*HD;

    float v0 = xr[tid], v1 = xr[tid+256], v2 = xr[tid+512];
    float ss = v0*v0 + v1*v1 + v2*v2;
    #pragma unroll
    for (int o = 16; o; o >>= 1) ss += __shfl_xor_sync(0xffffffffu, ss, o);
    if (lane == 0) red[wid] = ss;
    __syncthreads();
    if (tid == 0){
        float s = 0.f;
        #pragma unroll
        for (int i = 0; i < 8; i++) s += red[i];
        red[0] = rsqrtf(s * (1.0f/HD) + 1e-5f);
    }
    __syncthreads();
    const float inv = red[0];
    float t0 = v0*inv*nsc[tid], t1 = v1*inv*nsc[tid+256], t2 = v2*inv*nsc[tid+512];
    sh_t[tid] = t0; sh_t[tid+256] = t1; sh_t[tid+512] = t2;
    float* tb = g_t + (size_t)tok*HD;
    tb[tid]     = __uint_as_float(f2tf(t0));
    tb[tid+256] = __uint_as_float(f2tf(t1));
    tb[tid+512] = __uint_as_float(f2tf(t2));
    __syncthreads();

    // gate logits in fp32 (routing must match reference)
    for (int e = wid; e < NE; e += 8){
        float acc = 0.f;
        for (int i = lane; i < HD; i += 32) acc += sh_t[i]*gw[e*HD + i];
        #pragma unroll
        for (int o = 16; o; o >>= 1) acc += __shfl_xor_sync(0xffffffffu, acc, o);
        if (lane == 0) sh_g[e] = acc + gb[e];
    }
    __syncthreads();

    if (tid == 0){
        float v[NE];
        #pragma unroll
        for (int i = 0; i < NE; i++) v[i] = sh_g[i];
        bool used[NE] = {};
        int   bi[TK]; float bv[TK];
        for (int k = 0; k < TK; k++){
            float best = -1e30f; int b = 0;
            for (int i = 0; i < NE; i++)
                if (!used[i] && v[i] > best){ best = v[i]; b = i; }
            used[b] = true; bi[k] = b; bv[k] = best;
        }
        float m = bv[0], sum = 0.f, w[TK];
        #pragma unroll
        for (int k = 0; k < TK; k++){ w[k] = expf(bv[k]-m); sum += w[k]; }
        #pragma unroll
        for (int k = 0; k < TK; k++){
            g_top_idx[tok*TK+k] = bi[k];
            g_top_w[tok*TK+k]   = w[k]/sum;
            atomicAdd(&g_cnt[bi[k]], 1);
        }
    }
}

// ---------------- kernel 2: expert offsets ----------------
__global__ void k_offsets(){
    if (threadIdx.x == 0){
        int s = 0;
        for (int i = 0; i < NE; i++){ g_off[i] = s; s += g_cnt[i]; }
        g_off[NE] = s;
    }
}

// ---------------- kernel 3: scatter pairs sorted by expert ----------------
__global__ void k_scatter(){
    int t = blockIdx.x*blockDim.x + threadIdx.x;
    if (t >= NTOK) return;
    for (int k = 0; k < TK; k++){
        int e = g_top_idx[t*TK+k];
        int p = g_off[e] + atomicAdd(&g_cur[e], 1);
        g_pair_tok[p] = t;
        g_pair_w[p]   = g_top_w[t*TK+k];
        g_pos[t*TK+k] = p;
    }
}

// ---------------- grouped GEMM (tf32 mma), fused epilogues ----------------
// C[m,n] = sum_k A[m,k]*W[e][n,k]  (both K-major)
// G1: A = gathered g_t rows, epilogue = bias + swiglu -> g_act
// G2: A = g_act rows,        epilogue = (bias)*route_w -> g_y
template<int NTOT, int KTOT, bool G1>
__global__ void __launch_bounds__(256) k_gemm(
    const float* __restrict__ W, const float* __restrict__ Bias)
{
    const int e    = blockIdx.y;
    const int base = g_off[e];
    const int cnt  = g_off[e+1] - base;
    if (cnt <= 0) return;
    const int nt = blockIdx.x;

    __shared__ float As[128*20];
    __shared__ float Bs[64*20];

    const int tid  = threadIdx.x;
    const int lane = tid & 31, wid = tid >> 5;
    const int grp  = lane >> 2, tg = lane & 3;
    const int wm   = wid & 3,  wn = wid >> 2;

    // B tile loader mapping (fixed across mt): 64 rows x 16 cols, float4 per thread
    const int brow = tid >> 2, bq = tid & 3;
    const float* bp = W + (size_t)e*NTOT*KTOT + (size_t)(nt*64 + brow)*KTOT + bq*4;

    // A tile loader mapping: row = tid/2, two float4 quads per thread
    const int arow = tid >> 1;
    const int aq0  = (tid & 1) * 2;

    for (int mt = blockIdx.z; mt*128 < cnt; mt += gridDim.z){
        const int m0 = mt*128;
        const float* ap = nullptr;
        {
            int rg = m0 + arow;
            if (rg < cnt){
                if (G1) ap = g_t  + (size_t)g_pair_tok[base+rg]*HD;
                else    ap = g_act + (size_t)(base+rg)*ID;
            }
        }
        float c[2][4][4];
        #pragma unroll
        for (int i=0;i<2;i++)
            #pragma unroll
            for (int j=0;j<4;j++)
                #pragma unroll
                for (int l=0;l<4;l++) c[i][j][l] = 0.f;

        for (int kb = 0; kb < KTOT; kb += 16){
            #pragma unroll
            for (int i = 0; i < 2; i++){
                int q = aq0 + i;
                float4 v = make_float4(0.f,0.f,0.f,0.f);
                if (ap) v = *(const float4*)(ap + kb + q*4);
                float4 w4;
                w4.x = __uint_as_float(f2tf(v.x));
                w4.y = __uint_as_float(f2tf(v.y));
                w4.z = __uint_as_float(f2tf(v.z));
                w4.w = __uint_as_float(f2tf(v.w));
                *(float4*)&As[arow*20 + q*4] = w4;
            }
            {
                float4 v = *(const float4*)(bp + kb);
                float4 w4;
                w4.x = __uint_as_float(f2tf(v.x));
                w4.y = __uint_as_float(f2tf(v.y));
                w4.z = __uint_as_float(f2tf(v.z));
                w4.w = __uint_as_float(f2tf(v.w));
                *(float4*)&Bs[brow*20 + bq*4] = w4;
            }
            __syncthreads();
            #pragma unroll
            for (int ks = 0; ks < 2; ks++){
                const int k0 = ks*8;
                unsigned af[2][4];
                #pragma unroll
                for (int ma = 0; ma < 2; ma++){
                    int ra = wm*32 + ma*16 + grp;
                    af[ma][0] = __float_as_uint(As[ ra   *20 + k0+tg  ]);
                    af[ma][1] = __float_as_uint(As[(ra+8)*20 + k0+tg  ]);
                    af[ma][2] = __float_as_uint(As[ ra   *20 + k0+tg+4]);
                    af[ma][3] = __float_as_uint(As[(ra+8)*20 + k0+tg+4]);
                }
                #pragma unroll
                for (int na = 0; na < 4; na++){
                    int rb = wn*32 + na*8 + grp;
                    unsigned bf[2];
                    bf[0] = __float_as_uint(Bs[rb*20 + k0+tg  ]);
                    bf[1] = __float_as_uint(Bs[rb*20 + k0+tg+4]);
                    #pragma unroll
                    for (int ma = 0; ma < 2; ma++)
                        mma8(c[ma][na], af[ma], bf);
                }
            }
            __syncthreads();
        }
        // epilogue (global writes only; no smem reads -> safe before next iter's loads+sync)
        #pragma unroll
        for (int ma = 0; ma < 2; ma++){
            #pragma unroll
            for (int half = 0; half < 2; half++){
                int r = m0 + wm*32 + ma*16 + grp + half*8;
                if (r >= cnt) continue;
                int pos = base + r;
                #pragma unroll
                for (int na = 0; na < 4; na++){
                    int col = nt*64 + wn*32 + na*8 + 2*tg;
                    float v0 = c[ma][na][half*2+0];
                    float v1 = c[ma][na][half*2+1];
                    if (G1){
                        float glu = fminf(v0 + Bias[e*NTOT + col],     7.f);
                        float lin = fminf(fmaxf(v1 + Bias[e*NTOT + col + 1], -7.f), 7.f);
                        float s = 1.f/(1.f + __expf(-1.702f*glu));
                        g_act[(size_t)pos*ID + (col>>1)] =
                            __uint_as_float(f2tf(glu*s*(lin+1.f)));
                    } else {
                        float pw = g_pair_w[pos];
                        g_y[(size_t)pos*HD + col]     = (v0 + Bias[e*NTOT + col])     * pw;
                        g_y[(size_t)pos*HD + col + 1] = (v1 + Bias[e*NTOT + col + 1]) * pw;
                    }
                }
            }
        }
    }
}

// ---------------- kernel 6: combine: out = x + sum_k y ----------------
__global__ void __launch_bounds__(256) k_combine(
    const float* __restrict__ x, float* __restrict__ out)
{
    const int tok = blockIdx.x, tid = threadIdx.x;
    const int p0 = g_pos[tok*TK+0], p1 = g_pos[tok*TK+1];
    const int p2 = g_pos[tok*TK+2], p3 = g_pos[tok*TK+3];
    const float* y0 = g_y + (size_t)p0*HD;
    const float* y1 = g_y + (size_t)p1*HD;
    const float* y2 = g_y + (size_t)p2*HD;
    const float* y3 = g_y + (size_t)p3*HD;
    const float* xr = x + (size_t)tok*HD;
    float* orow = out + (size_t)tok*HD;
    #pragma unroll
    for (int j = 0; j < 3; j++){
        int h = tid + j*256;
        orow[h] = xr[h] + y0[h] + y1[h] + y2[h] + y3[h];
    }
}

// ---------------- launch ----------------
extern "C" void kernel_launch(void* const* d_in, const int* in_sizes, int n_in,
                              void* d_out, int out_size)
{
    const float* x   = (const float*)d_in[0];
    const float* nsc = (const float*)d_in[1];
    const float* gw  = (const float*)d_in[2];
    const float* gb  = (const float*)d_in[3];
    const float* w1  = (const float*)d_in[4];
    const float* b1  = (const float*)d_in[5];
    const float* w2  = (const float*)d_in[6];
    const float* b2  = (const float*)d_in[7];
    float* out = (float*)d_out;

    k_reset<<<1, 32>>>();
    k_norm_gate<<<NTOK, 256>>>(x, nsc, gw, gb);
    k_offsets<<<1, 32>>>();
    k_scatter<<<NTOK/256, 256>>>();
    k_gemm<N1, HD, true ><<<dim3(N1/64, NE, 8), 256>>>(w1, b1);
    k_gemm<HD, ID, false><<<dim3(HD/64, NE, 8), 256>>>(w2, b2);
    k_combine<<<NTOK, 256>>>(x, out);
}

// round 4
// speedup vs baseline: 1.2632x; 1.2632x over previous
#include <cuda_runtime.h>
#include <cstdint>

#define NTOK 2048
#define HD   768
#define ID   1536
#define N1   3072
#define NE   16
#define TK   4
#define NPAIR (NTOK*TK)

// ---------------- scratch (static, no allocs) ----------------
__device__ __align__(16) float g_t[(size_t)NTOK*HD];      // rmsnorm'd tokens (tf32-rounded)
__device__ __align__(16) float g_act[(size_t)NPAIR*ID];   // swiglu activations (tf32-rounded)
__device__ __align__(16) float g_y[(size_t)NPAIR*HD];     // weighted expert outputs per pair
__device__ int   g_top_idx[NTOK*TK];
__device__ float g_top_w[NTOK*TK];
__device__ int   g_cnt[NE];
__device__ int   g_off[NE+1];
__device__ int   g_cur[NE];
__device__ int   g_pair_tok[NPAIR];
__device__ float g_pair_w[NPAIR];
__device__ int   g_pos[NPAIR];

__device__ __forceinline__ unsigned f2tf(float x){
    unsigned u; asm("cvt.rna.tf32.f32 %0, %1;" : "=r"(u) : "f"(x)); return u;
}

__device__ __forceinline__ void mma8(float c[4], const unsigned a[4], const unsigned b[2]){
    asm volatile(
        "mma.sync.aligned.m16n8k8.row.col.f32.tf32.tf32.f32 "
        "{%0,%1,%2,%3},{%4,%5,%6,%7},{%8,%9},{%0,%1,%2,%3};\n"
        : "+f"(c[0]), "+f"(c[1]), "+f"(c[2]), "+f"(c[3])
        : "r"(a[0]), "r"(a[1]), "r"(a[2]), "r"(a[3]), "r"(b[0]), "r"(b[1]));
}

// ---------------- kernel 0: reset counters ----------------
__global__ void k_reset(){
    int i = threadIdx.x;
    if (i < NE){ g_cnt[i] = 0; g_cur[i] = 0; }
}

// ---------------- kernel 1: rmsnorm + gate + top4 ----------------
__global__ void __launch_bounds__(256) k_norm_gate(
    const float* __restrict__ x, const float* __restrict__ nsc,
    const float* __restrict__ gw, const float* __restrict__ gb)
{
    __shared__ float sh_t[HD];
    __shared__ float red[8];
    __shared__ float sh_g[NE];
    const int tok = blockIdx.x, tid = threadIdx.x;
    const int lane = tid & 31, wid = tid >> 5;
    const float* xr = x + (size_t)tok*HD;

    float v0 = xr[tid], v1 = xr[tid+256], v2 = xr[tid+512];
    float ss = v0*v0 + v1*v1 + v2*v2;
    #pragma unroll
    for (int o = 16; o; o >>= 1) ss += __shfl_xor_sync(0xffffffffu, ss, o);
    if (lane == 0) red[wid] = ss;
    __syncthreads();
    if (tid == 0){
        float s = 0.f;
        #pragma unroll
        for (int i = 0; i < 8; i++) s += red[i];
        red[0] = rsqrtf(s * (1.0f/HD) + 1e-5f);
    }
    __syncthreads();
    const float inv = red[0];
    float t0 = v0*inv*nsc[tid], t1 = v1*inv*nsc[tid+256], t2 = v2*inv*nsc[tid+512];
    sh_t[tid] = t0; sh_t[tid+256] = t1; sh_t[tid+512] = t2;
    float* tb = g_t + (size_t)tok*HD;
    tb[tid]     = __uint_as_float(f2tf(t0));
    tb[tid+256] = __uint_as_float(f2tf(t1));
    tb[tid+512] = __uint_as_float(f2tf(t2));
    __syncthreads();

    // gate logits in fp32 (routing must match reference)
    for (int e = wid; e < NE; e += 8){
        float acc = 0.f;
        for (int i = lane; i < HD; i += 32) acc += sh_t[i]*gw[e*HD + i];
        #pragma unroll
        for (int o = 16; o; o >>= 1) acc += __shfl_xor_sync(0xffffffffu, acc, o);
        if (lane == 0) sh_g[e] = acc + gb[e];
    }
    __syncthreads();

    if (tid == 0){
        float v[NE];
        #pragma unroll
        for (int i = 0; i < NE; i++) v[i] = sh_g[i];
        bool used[NE] = {};
        int   bi[TK]; float bv[TK];
        for (int k = 0; k < TK; k++){
            float best = -1e30f; int b = 0;
            for (int i = 0; i < NE; i++)
                if (!used[i] && v[i] > best){ best = v[i]; b = i; }
            used[b] = true; bi[k] = b; bv[k] = best;
        }
        float m = bv[0], sum = 0.f, w[TK];
        #pragma unroll
        for (int k = 0; k < TK; k++){ w[k] = expf(bv[k]-m); sum += w[k]; }
        #pragma unroll
        for (int k = 0; k < TK; k++){
            g_top_idx[tok*TK+k] = bi[k];
            g_top_w[tok*TK+k]   = w[k]/sum;
            atomicAdd(&g_cnt[bi[k]], 1);
        }
    }
}

// ---------------- kernel 2: expert offsets ----------------
__global__ void k_offsets(){
    if (threadIdx.x == 0){
        int s = 0;
        for (int i = 0; i < NE; i++){ g_off[i] = s; s += g_cnt[i]; }
        g_off[NE] = s;
    }
}

// ---------------- kernel 3: scatter pairs sorted by expert ----------------
__global__ void k_scatter(){
    int t = blockIdx.x*blockDim.x + threadIdx.x;
    if (t >= NTOK) return;
    for (int k = 0; k < TK; k++){
        int e = g_top_idx[t*TK+k];
        int p = g_off[e] + atomicAdd(&g_cur[e], 1);
        g_pair_tok[p] = t;
        g_pair_w[p]   = g_top_w[t*TK+k];
        g_pos[t*TK+k] = p;
    }
}

// ---------------- grouped GEMM (tf32 mma), register-staged double buffer ----
// C[m,n] = sum_k A[m,k]*W[e][n,k]  (both K-major).
// A operands are tf32-rounded in memory; W is raw fp32 (tf32 MMA datapath
// truncates to the tf32 bits -> implicit RZ, within error budget).
// Tiles: CTA 128x128x16, warp 64x32 (warp grid 2(M) x 4(N)).
// Pipeline: LDG tile k+1 -> compute tile k (hides latency) -> STS -> sync.
template<int NTOT, int KTOT, bool G1>
__global__ void __launch_bounds__(256,2) k_gemm2(
    const float* __restrict__ W, const float* __restrict__ Bias)
{
    const int e    = blockIdx.y;
    const int base = g_off[e];
    const int cnt  = g_off[e+1] - base;
    if (cnt <= 0) return;
    const int nt = blockIdx.x;

    __shared__ float As[2][128*20];
    __shared__ float Bs[2][128*20];

    const int tid  = threadIdx.x;
    const int lane = tid & 31, wid = tid >> 5;
    const int grp  = lane >> 2, tg = lane & 3;
    const int wm   = wid & 1,  wn = wid >> 1;

    // loader mapping: 256 threads cover 128 rows x 16 cols, 2 float4 each
    const int lrow = tid >> 1;
    const int lq   = (tid & 1) * 2;   // quad index 0 or 2 (two consecutive quads)

    const float* wrow = W + (size_t)e*NTOT*KTOT + (size_t)(nt*128 + lrow)*KTOT + lq*4;

    for (int mt = blockIdx.z; mt*128 < cnt; mt += gridDim.z){
        const int m0 = mt*128;
        // OOB A rows read a valid dummy row (g_t row 0); epilogue masks them.
        const float* ap;
        {
            int rg = m0 + lrow;
            if (rg < cnt){
                ap = G1 ? g_t   + (size_t)g_pair_tok[base+rg]*HD
                        : g_act + (size_t)(base+rg)*ID;
            } else {
                ap = g_t;
            }
            ap += lq*4;
        }

        float c[4][4][4];
        #pragma unroll
        for (int i=0;i<4;i++)
            #pragma unroll
            for (int j=0;j<4;j++)
                #pragma unroll
                for (int l=0;l<4;l++) c[i][j][l] = 0.f;

        // ---- prologue: load tile 0 -> regs -> smem buf0 ----
        float4 ra0 = *(const float4*)(ap);
        float4 ra1 = *(const float4*)(ap + 4);
        float4 rb0 = *(const float4*)(wrow);
        float4 rb1 = *(const float4*)(wrow + 4);
        *(float4*)&As[0][lrow*20 + lq*4]     = ra0;
        *(float4*)&As[0][lrow*20 + lq*4 + 4] = ra1;
        *(float4*)&Bs[0][lrow*20 + lq*4]     = rb0;
        *(float4*)&Bs[0][lrow*20 + lq*4 + 4] = rb1;
        __syncthreads();

        int buf = 0;
        #pragma unroll 1
        for (int kb = 16; kb < KTOT; kb += 16){
            // issue loads for next tile (latency hidden behind compute below)
            ra0 = *(const float4*)(ap   + kb);
            ra1 = *(const float4*)(ap   + kb + 4);
            rb0 = *(const float4*)(wrow + kb);
            rb1 = *(const float4*)(wrow + kb + 4);

            // compute current tile from smem[buf]
            #pragma unroll
            for (int ks = 0; ks < 2; ks++){
                const int k0 = ks*8;
                unsigned af[4][4];
                #pragma unroll
                for (int ma = 0; ma < 4; ma++){
                    int rr = wm*64 + ma*16 + grp;
                    af[ma][0] = __float_as_uint(As[buf][ rr   *20 + k0+tg  ]);
                    af[ma][1] = __float_as_uint(As[buf][(rr+8)*20 + k0+tg  ]);
                    af[ma][2] = __float_as_uint(As[buf][ rr   *20 + k0+tg+4]);
                    af[ma][3] = __float_as_uint(As[buf][(rr+8)*20 + k0+tg+4]);
                }
                #pragma unroll
                for (int na = 0; na < 4; na++){
                    int rb = wn*32 + na*8 + grp;
                    unsigned bfr[2];
                    bfr[0] = __float_as_uint(Bs[buf][rb*20 + k0+tg  ]);
                    bfr[1] = __float_as_uint(Bs[buf][rb*20 + k0+tg+4]);
                    #pragma unroll
                    for (int ma = 0; ma < 4; ma++) mma8(c[ma][na], af[ma], bfr);
                }
            }

            // stage next tile into the other buffer
            const int nb = buf ^ 1;
            *(float4*)&As[nb][lrow*20 + lq*4]     = ra0;
            *(float4*)&As[nb][lrow*20 + lq*4 + 4] = ra1;
            *(float4*)&Bs[nb][lrow*20 + lq*4]     = rb0;
            *(float4*)&Bs[nb][lrow*20 + lq*4 + 4] = rb1;
            __syncthreads();
            buf = nb;
        }

        // ---- last tile compute ----
        #pragma unroll
        for (int ks = 0; ks < 2; ks++){
            const int k0 = ks*8;
            unsigned af[4][4];
            #pragma unroll
            for (int ma = 0; ma < 4; ma++){
                int rr = wm*64 + ma*16 + grp;
                af[ma][0] = __float_as_uint(As[buf][ rr   *20 + k0+tg  ]);
                af[ma][1] = __float_as_uint(As[buf][(rr+8)*20 + k0+tg  ]);
                af[ma][2] = __float_as_uint(As[buf][ rr   *20 + k0+tg+4]);
                af[ma][3] = __float_as_uint(As[buf][(rr+8)*20 + k0+tg+4]);
            }
            #pragma unroll
            for (int na = 0; na < 4; na++){
                int rb = wn*32 + na*8 + grp;
                unsigned bfr[2];
                bfr[0] = __float_as_uint(Bs[buf][rb*20 + k0+tg  ]);
                bfr[1] = __float_as_uint(Bs[buf][rb*20 + k0+tg+4]);
                #pragma unroll
                for (int ma = 0; ma < 4; ma++) mma8(c[ma][na], af[ma], bfr);
            }
        }
        __syncthreads();   // smem reusable next mt iteration

        // ---- epilogue (global writes only) ----
        #pragma unroll
        for (int ma = 0; ma < 4; ma++){
            #pragma unroll
            for (int half = 0; half < 2; half++){
                int r = m0 + wm*64 + ma*16 + grp + half*8;
                if (r >= cnt) continue;
                int pos = base + r;
                #pragma unroll
                for (int na = 0; na < 4; na++){
                    int col = nt*128 + wn*32 + na*8 + 2*tg;
                    float v0 = c[ma][na][half*2+0];
                    float v1 = c[ma][na][half*2+1];
                    if (G1){
                        float glu = fminf(v0 + Bias[e*NTOT + col],     7.f);
                        float lin = fminf(fmaxf(v1 + Bias[e*NTOT + col + 1], -7.f), 7.f);
                        float s = 1.f/(1.f + __expf(-1.702f*glu));
                        g_act[(size_t)pos*ID + (col>>1)] =
                            __uint_as_float(f2tf(glu*s*(lin+1.f)));
                    } else {
                        float pw = g_pair_w[pos];
                        g_y[(size_t)pos*HD + col]     = (v0 + Bias[e*NTOT + col])     * pw;
                        g_y[(size_t)pos*HD + col + 1] = (v1 + Bias[e*NTOT + col + 1]) * pw;
                    }
                }
            }
        }
    }
}

// ---------------- kernel 6: combine: out = x + sum_k y ----------------
__global__ void __launch_bounds__(256) k_combine(
    const float* __restrict__ x, float* __restrict__ out)
{
    const int tok = blockIdx.x, tid = threadIdx.x;
    const int p0 = g_pos[tok*TK+0], p1 = g_pos[tok*TK+1];
    const int p2 = g_pos[tok*TK+2], p3 = g_pos[tok*TK+3];
    const float* y0 = g_y + (size_t)p0*HD;
    const float* y1 = g_y + (size_t)p1*HD;
    const float* y2 = g_y + (size_t)p2*HD;
    const float* y3 = g_y + (size_t)p3*HD;
    const float* xr = x + (size_t)tok*HD;
    float* orow = out + (size_t)tok*HD;
    #pragma unroll
    for (int j = 0; j < 3; j++){
        int h = tid + j*256;
        orow[h] = xr[h] + y0[h] + y1[h] + y2[h] + y3[h];
    }
}

// ---------------- launch ----------------
extern "C" void kernel_launch(void* const* d_in, const int* in_sizes, int n_in,
                              void* d_out, int out_size)
{
    const float* x   = (const float*)d_in[0];
    const float* nsc = (const float*)d_in[1];
    const float* gw  = (const float*)d_in[2];
    const float* gb  = (const float*)d_in[3];
    const float* w1  = (const float*)d_in[4];
    const float* b1  = (const float*)d_in[5];
    const float* w2  = (const float*)d_in[6];
    const float* b2  = (const float*)d_in[7];
    float* out = (float*)d_out;

    k_reset<<<1, 32>>>();
    k_norm_gate<<<NTOK, 256>>>(x, nsc, gw, gb);
    k_offsets<<<1, 32>>>();
    k_scatter<<<NTOK/256, 256>>>();
    k_gemm2<N1, HD, true ><<<dim3(N1/128, NE, 8), 256>>>(w1, b1);
    k_gemm2<HD, ID, false><<<dim3(HD/128, NE, 8), 256>>>(w2, b2);
    k_combine<<<NTOK, 256>>>(x, out);
}